// round 3
// baseline (speedup 1.0000x reference)
#include <cuda_runtime.h>

#define SEQ   262144
#define HID   20
#define INP   9
#define CH    512          // output chunk per block
#define WARM  256          // warmup steps (state convergence)
#define GROUP 16           // pipeline sync granularity (steps)
#define RING  64           // h1 ring buffer depth (steps)
#define NBLK  (SEQ / CH)   // 512 blocks

__device__ __forceinline__ float sigf(float v) {
    return __fdividef(1.f, 1.f + __expf(-v));
}
__device__ __forceinline__ float tanhf_(float v) {
    return 1.f - __fdividef(2.f, __expf(2.f * v) + 1.f);
}

__global__ void __launch_bounds__(64, 4) lstm_kernel(
    const float* __restrict__ x,
    const float* __restrict__ w_ih1, const float* __restrict__ w_hh1, const float* __restrict__ b1,
    const float* __restrict__ w_ih2, const float* __restrict__ w_hh2, const float* __restrict__ b2,
    const float* __restrict__ w_p,  const float* __restrict__ b_p,
    float* __restrict__ out)
{
    __shared__ float ring[RING][HID];
    __shared__ int g_prod;
    __shared__ int g_cons;

    const int tid  = threadIdx.x;
    const int warp = tid >> 5;
    const int lane = tid & 31;
    const int k    = (lane < HID) ? lane : (HID - 1);
    const bool active = (lane < HID);

    if (tid == 0) { g_prod = -1; g_cons = -1; }
    __syncthreads();

    const int blk       = blockIdx.x;
    const int out_begin = blk * CH;
    const int start     = (blk == 0) ? 0 : (out_begin - WARM);
    const int nsteps    = out_begin + CH - start;   // multiple of GROUP

    volatile int* vp = &g_prod;
    volatile int* vc = &g_cons;

    if (warp == 0) {
        // ---------------- layer 1 (producer) ----------------
        float wih[4][INP], whh[4][HID], bb[4];
        #pragma unroll
        for (int g = 0; g < 4; g++) {
            const int row = g * HID + k;
            #pragma unroll
            for (int j = 0; j < INP; j++) wih[g][j] = w_ih1[row * INP + j];
            #pragma unroll
            for (int j = 0; j < HID; j++) whh[g][j] = w_hh1[row * HID + j];
            bb[g] = b1[row];
        }
        float h = 0.f, c = 0.f;

        float xc[INP];
        #pragma unroll
        for (int j = 0; j < INP; j++) xc[j] = x[(long)start * INP + j];

        for (int s = 0; s < nsteps; s++) {
            if ((s & (GROUP - 1)) == 0) {
                const int g = s / GROUP;
                if (g >= RING / GROUP) {
                    // backpressure: don't overwrite unconsumed ring slots
                    while (*vc < g - RING / GROUP) { __nanosleep(32); }
                }
            }
            const int t = start + s;

            // prefetch next x (clamped at sequence end)
            float xn[INP];
            const long tn = (t + 1 < SEQ) ? (long)(t + 1) * INP : (long)t * INP;
            #pragma unroll
            for (int j = 0; j < INP; j++) xn[j] = x[tn + j];

            float a0 = bb[0], a1 = bb[1], a2 = bb[2], a3 = bb[3];
            #pragma unroll
            for (int j = 0; j < INP; j++) {
                a0 = fmaf(xc[j], wih[0][j], a0);
                a1 = fmaf(xc[j], wih[1][j], a1);
                a2 = fmaf(xc[j], wih[2][j], a2);
                a3 = fmaf(xc[j], wih[3][j], a3);
            }
            #pragma unroll
            for (int j = 0; j < HID; j++) {
                const float hj = __shfl_sync(0xffffffffu, h, j);
                a0 = fmaf(hj, whh[0][j], a0);
                a1 = fmaf(hj, whh[1][j], a1);
                a2 = fmaf(hj, whh[2][j], a2);
                a3 = fmaf(hj, whh[3][j], a3);
            }
            const float ig = sigf(a0);
            const float fg = sigf(a1);
            const float gg = tanhf_(a2);
            const float og = sigf(a3);
            c = fg * c + ig * gg;
            h = og * tanhf_(c);

            if (active) ring[s & (RING - 1)][k] = h;

            #pragma unroll
            for (int j = 0; j < INP; j++) xc[j] = xn[j];

            if ((s & (GROUP - 1)) == GROUP - 1) {
                __threadfence_block();
                if (lane == 0) *vp = s / GROUP;
            }
        }
    } else {
        // ---------------- layer 2 + projection (consumer) ----------------
        float wih[4][HID], whh[4][HID], bb[4];
        #pragma unroll
        for (int g = 0; g < 4; g++) {
            const int row = g * HID + k;
            #pragma unroll
            for (int j = 0; j < HID; j++) wih[g][j] = w_ih2[row * HID + j];
            #pragma unroll
            for (int j = 0; j < HID; j++) whh[g][j] = w_hh2[row * HID + j];
            bb[g] = b2[row];
        }
        const float wp = active ? w_p[k] : 0.f;
        const float bp = b_p[0];
        float h = 0.f, c = 0.f;

        for (int s = 0; s < nsteps; s++) {
            if ((s & (GROUP - 1)) == 0) {
                const int g = s / GROUP;
                while (*vp < g) { __nanosleep(32); }
                __threadfence_block();
            }
            const int t = start + s;

            const float h1 = ring[s & (RING - 1)][k];

            float a0 = bb[0], a1 = bb[1], a2 = bb[2], a3 = bb[3];
            #pragma unroll
            for (int j = 0; j < HID; j++) {
                const float h1j = __shfl_sync(0xffffffffu, h1, j);
                const float h2j = __shfl_sync(0xffffffffu, h,  j);
                a0 = fmaf(h1j, wih[0][j], a0);
                a1 = fmaf(h1j, wih[1][j], a1);
                a2 = fmaf(h1j, wih[2][j], a2);
                a3 = fmaf(h1j, wih[3][j], a3);
                a0 = fmaf(h2j, whh[0][j], a0);
                a1 = fmaf(h2j, whh[1][j], a1);
                a2 = fmaf(h2j, whh[2][j], a2);
                a3 = fmaf(h2j, whh[3][j], a3);
            }
            const float ig = sigf(a0);
            const float fg = sigf(a1);
            const float gg = tanhf_(a2);
            const float og = sigf(a3);
            c = fg * c + ig * gg;
            h = og * tanhf_(c);

            if (t >= out_begin) {
                float p = active ? (wp * h) : 0.f;
                #pragma unroll
                for (int off = 16; off; off >>= 1)
                    p += __shfl_down_sync(0xffffffffu, p, off);
                if (lane == 0) out[t] = p + bp;
            }

            if ((s & (GROUP - 1)) == GROUP - 1) {
                __threadfence_block();
                if (lane == 0) *vc = s / GROUP;
            }
        }
    }
}

extern "C" void kernel_launch(void* const* d_in, const int* in_sizes, int n_in,
                              void* d_out, int out_size)
{
    const float* x     = (const float*)d_in[0];
    const float* w_ih1 = (const float*)d_in[1];
    const float* w_hh1 = (const float*)d_in[2];
    const float* b1    = (const float*)d_in[3];
    const float* w_ih2 = (const float*)d_in[4];
    const float* w_hh2 = (const float*)d_in[5];
    const float* b2    = (const float*)d_in[6];
    const float* w_p   = (const float*)d_in[7];
    const float* b_p   = (const float*)d_in[8];
    float* out = (float*)d_out;

    lstm_kernel<<<NBLK, 64>>>(x, w_ih1, w_hh1, b1, w_ih2, w_hh2, b2, w_p, b_p, out);
}

// round 4
// speedup vs baseline: 1.2929x; 1.2929x over previous
#include <cuda_runtime.h>

#define SEQ   262144
#define HID   20
#define INP   9
#define CH    512          // output chunk per block
#define WARM  128          // warmup steps (state convergence)
#define GROUP 16           // pipeline sync granularity (steps)
#define RING  64           // ring buffer depth (steps), 4 groups
#define NBLK  (SEQ / CH)   // 512 blocks

__device__ __forceinline__ float sigf(float v) {
    return __fdividef(1.f, 1.f + __expf(-v));
}
__device__ __forceinline__ float tanhf_(float v) {
    return 1.f - __fdividef(2.f, __expf(2.f * v) + 1.f);
}

__global__ void __launch_bounds__(96, 4) lstm_kernel(
    const float* __restrict__ x,
    const float* __restrict__ w_ih1, const float* __restrict__ w_hh1, const float* __restrict__ b1,
    const float* __restrict__ w_ih2, const float* __restrict__ w_hh2, const float* __restrict__ b2,
    const float* __restrict__ w_p,  const float* __restrict__ b_p,
    float* __restrict__ out)
{
    __shared__ float ring1[RING][HID];       // h1 per step
    __shared__ float ring2[RING][4][HID];    // layer2 gate preacts (input part) per step
    __shared__ int f1, f2, f3;               // progress flags (group index) per stage

    const int tid  = threadIdx.x;
    const int warp = tid >> 5;
    const int lane = tid & 31;
    const int k    = (lane < HID) ? lane : (HID - 1);
    const bool active = (lane < HID);

    if (tid == 0) { f1 = -1; f2 = -1; f3 = -1; }
    __syncthreads();

    const int blk       = blockIdx.x;
    const int out_begin = blk * CH;
    const int start     = (blk == 0) ? 0 : (out_begin - WARM);
    const int nsteps    = out_begin + CH - start;   // multiple of GROUP

    volatile int* vf1 = &f1;
    volatile int* vf2 = &f2;
    volatile int* vf3 = &f3;

    if (warp == 0) {
        // ================= stage 0: layer-1 recurrence =================
        float wih[4][INP], whh[4][HID], bb[4];
        #pragma unroll
        for (int g = 0; g < 4; g++) {
            const int row = g * HID + k;
            #pragma unroll
            for (int j = 0; j < INP; j++) wih[g][j] = w_ih1[row * INP + j];
            #pragma unroll
            for (int j = 0; j < HID; j++) whh[g][j] = w_hh1[row * HID + j];
            bb[g] = b1[row];
        }
        float h = 0.f, c = 0.f;

        float xc[INP];
        #pragma unroll
        for (int j = 0; j < INP; j++) xc[j] = x[(long)start * INP + j];

        for (int s = 0; s < nsteps; s++) {
            if ((s & (GROUP - 1)) == 0) {
                const int g = s >> 4;
                if (g >= RING / GROUP) {
                    while (*vf2 < g - RING / GROUP) { __nanosleep(32); }
                }
            }
            const int t = start + s;

            // prefetch next x (clamped at sequence end)
            float xn[INP];
            const long tn = (t + 1 < SEQ) ? (long)(t + 1) * INP : (long)t * INP;
            #pragma unroll
            for (int j = 0; j < INP; j++) xn[j] = x[tn + j];

            // split accumulators: x-part and two h-part chains per gate
            float ax[4], ah0[4], ah1[4];
            #pragma unroll
            for (int g = 0; g < 4; g++) { ax[g] = bb[g]; ah0[g] = 0.f; ah1[g] = 0.f; }
            #pragma unroll
            for (int j = 0; j < INP; j++) {
                #pragma unroll
                for (int g = 0; g < 4; g++) ax[g] = fmaf(xc[j], wih[g][j], ax[g]);
            }
            #pragma unroll
            for (int j = 0; j < HID / 2; j++) {
                const float hj0 = __shfl_sync(0xffffffffu, h, j);
                const float hj1 = __shfl_sync(0xffffffffu, h, j + HID / 2);
                #pragma unroll
                for (int g = 0; g < 4; g++) {
                    ah0[g] = fmaf(hj0, whh[g][j], ah0[g]);
                    ah1[g] = fmaf(hj1, whh[g][j + HID / 2], ah1[g]);
                }
            }
            const float ig = sigf(ax[0] + (ah0[0] + ah1[0]));
            const float fg = sigf(ax[1] + (ah0[1] + ah1[1]));
            const float gg = tanhf_(ax[2] + (ah0[2] + ah1[2]));
            const float og = sigf(ax[3] + (ah0[3] + ah1[3]));
            c = fg * c + ig * gg;
            h = og * tanhf_(c);

            if (active) ring1[s & (RING - 1)][k] = h;

            #pragma unroll
            for (int j = 0; j < INP; j++) xc[j] = xn[j];

            if ((s & (GROUP - 1)) == GROUP - 1) {
                __threadfence_block();
                if (lane == 0) *vf1 = s >> 4;
            }
        }
    } else if (warp == 1) {
        // ====== stage 1: layer-2 input projection (feedforward) ======
        float wih[4][HID], bb[4];
        #pragma unroll
        for (int g = 0; g < 4; g++) {
            const int row = g * HID + k;
            #pragma unroll
            for (int j = 0; j < HID; j++) wih[g][j] = w_ih2[row * HID + j];
            bb[g] = b2[row];
        }

        for (int s = 0; s < nsteps; s++) {
            if ((s & (GROUP - 1)) == 0) {
                const int g = s >> 4;
                while (*vf1 < g) { __nanosleep(32); }
                if (g >= RING / GROUP) {
                    while (*vf3 < g - RING / GROUP) { __nanosleep(32); }
                }
                __threadfence_block();
            }

            const float h1 = ring1[s & (RING - 1)][k];

            float a0[4], a1[4];
            #pragma unroll
            for (int g = 0; g < 4; g++) { a0[g] = bb[g]; a1[g] = 0.f; }
            #pragma unroll
            for (int j = 0; j < HID / 2; j++) {
                const float hj0 = __shfl_sync(0xffffffffu, h1, j);
                const float hj1 = __shfl_sync(0xffffffffu, h1, j + HID / 2);
                #pragma unroll
                for (int g = 0; g < 4; g++) {
                    a0[g] = fmaf(hj0, wih[g][j], a0[g]);
                    a1[g] = fmaf(hj1, wih[g][j + HID / 2], a1[g]);
                }
            }
            if (active) {
                #pragma unroll
                for (int g = 0; g < 4; g++)
                    ring2[s & (RING - 1)][g][k] = a0[g] + a1[g];
            }

            if ((s & (GROUP - 1)) == GROUP - 1) {
                __threadfence_block();
                if (lane == 0) *vf2 = s >> 4;
            }
        }
    } else {
        // ====== stage 2: layer-2 recurrence + output projection ======
        float whh[4][HID];
        #pragma unroll
        for (int g = 0; g < 4; g++) {
            const int row = g * HID + k;
            #pragma unroll
            for (int j = 0; j < HID; j++) whh[g][j] = w_hh2[row * HID + j];
        }
        const float wp = active ? w_p[k] : 0.f;
        const float bp = b_p[0];
        float h = 0.f, c = 0.f;

        for (int s = 0; s < nsteps; s++) {
            if ((s & (GROUP - 1)) == 0) {
                const int g = s >> 4;
                while (*vf2 < g) { __nanosleep(32); }
                __threadfence_block();
            }
            const int t = start + s;
            const int sl = s & (RING - 1);

            float ap[4];
            #pragma unroll
            for (int g = 0; g < 4; g++) ap[g] = ring2[sl][g][k];

            float a0[4], a1[4];
            #pragma unroll
            for (int g = 0; g < 4; g++) { a0[g] = ap[g]; a1[g] = 0.f; }
            #pragma unroll
            for (int j = 0; j < HID / 2; j++) {
                const float hj0 = __shfl_sync(0xffffffffu, h, j);
                const float hj1 = __shfl_sync(0xffffffffu, h, j + HID / 2);
                #pragma unroll
                for (int g = 0; g < 4; g++) {
                    a0[g] = fmaf(hj0, whh[g][j], a0[g]);
                    a1[g] = fmaf(hj1, whh[g][j + HID / 2], a1[g]);
                }
            }
            const float ig = sigf(a0[0] + a1[0]);
            const float fg = sigf(a0[1] + a1[1]);
            const float gg = tanhf_(a0[2] + a1[2]);
            const float og = sigf(a0[3] + a1[3]);
            c = fg * c + ig * gg;
            h = og * tanhf_(c);

            if (t >= out_begin) {
                float p = active ? (wp * h) : 0.f;
                #pragma unroll
                for (int off = 16; off; off >>= 1)
                    p += __shfl_down_sync(0xffffffffu, p, off);
                if (lane == 0) out[t] = p + bp;
            }

            if ((s & (GROUP - 1)) == GROUP - 1) {
                __threadfence_block();
                if (lane == 0) *vf3 = s >> 4;
            }
        }
    }
}

extern "C" void kernel_launch(void* const* d_in, const int* in_sizes, int n_in,
                              void* d_out, int out_size)
{
    const float* x     = (const float*)d_in[0];
    const float* w_ih1 = (const float*)d_in[1];
    const float* w_hh1 = (const float*)d_in[2];
    const float* b1    = (const float*)d_in[3];
    const float* w_ih2 = (const float*)d_in[4];
    const float* w_hh2 = (const float*)d_in[5];
    const float* b2    = (const float*)d_in[6];
    const float* w_p   = (const float*)d_in[7];
    const float* b_p   = (const float*)d_in[8];
    float* out = (float*)d_out;

    lstm_kernel<<<NBLK, 96>>>(x, w_ih1, w_hh1, b1, w_ih2, w_hh2, b2, w_p, b_p, out);
}

// round 6
// speedup vs baseline: 1.4714x; 1.1380x over previous
#include <cuda_runtime.h>

#define SEQ    262144
#define HID    20
#define INP    9
#define CH     448          // output chunk per block
#define WARM   96           // warmup steps (state convergence)
#define GROUP  16           // pipeline sync granularity (steps)
#define RING   64           // ring depth (steps) = 4 groups
#define AHEAD  48           // xg1 computed 3 groups ahead
#define NBLK   ((SEQ + CH - 1) / CH)   // 586 blocks (<= 592 one-wave capacity)

typedef unsigned long long u64;

__device__ __forceinline__ u64 pk2(float lo, float hi) {
    u64 r; asm("mov.b64 %0,{%1,%2};" : "=l"(r) : "f"(lo), "f"(hi)); return r;
}
__device__ __forceinline__ void up2(u64 v, float& lo, float& hi) {
    asm("mov.b64 {%0,%1},%2;" : "=f"(lo), "=f"(hi) : "l"(v));
}
__device__ __forceinline__ u64 fma2(u64 a, u64 b, u64 c) {
    u64 d; asm("fma.rn.f32x2 %0,%1,%2,%3;" : "=l"(d) : "l"(a), "l"(b), "l"(c)); return d;
}

__device__ __forceinline__ float sigf(float v) {
    return __fdividef(1.f, 1.f + __expf(-v));
}
__device__ __forceinline__ float tanhf_(float v) {
    return 1.f - __fdividef(2.f, __expf(2.f * v) + 1.f);
}

__global__ void __launch_bounds__(96, 4) lstm_kernel(
    const float* __restrict__ x,
    const float* __restrict__ w_ih1, const float* __restrict__ w_hh1, const float* __restrict__ b1,
    const float* __restrict__ w_ih2, const float* __restrict__ w_hh2, const float* __restrict__ b2,
    const float* __restrict__ w_p,  const float* __restrict__ b_p,
    float* __restrict__ out)
{
    __shared__ float ring0[RING][HID][4];   // layer-1 input preacts (incl b1), float4 per unit
    __shared__ float ring1[RING][HID];      // h1 per step
    __shared__ float ring2[RING][HID][4];   // layer-2 input preacts (incl b2), float4 per unit
    __shared__ int f0, f1, f2, f3;          // highest completed group per resource

    const int tid  = threadIdx.x;
    const int warp = tid >> 5;
    const int lane = tid & 31;
    const int k    = (lane < HID) ? lane : (HID - 1);
    const bool active = (lane < HID);

    if (tid == 0) { f0 = -1; f1 = -1; f2 = -1; f3 = -1; }
    __syncthreads();

    const int blk       = blockIdx.x;
    const int out_begin = blk * CH;
    const int out_end   = (out_begin + CH < SEQ) ? (out_begin + CH) : SEQ;
    const int start     = (blk == 0) ? 0 : (out_begin - WARM);
    const int nsteps    = out_end - start;          // multiple of GROUP

    volatile int* vf0 = &f0;
    volatile int* vf1 = &f1;
    volatile int* vf2 = &f2;
    volatile int* vf3 = &f3;

    if (warp == 0) {
        // ============ stage 0: layer-1 recurrence (pure) ============
        u64 whhp[4][HID / 2];
        #pragma unroll
        for (int g = 0; g < 4; g++) {
            const int row = g * HID + k;
            #pragma unroll
            for (int i = 0; i < HID / 2; i++)
                whhp[g][i] = pk2(w_hh1[row * HID + 2 * i], w_hh1[row * HID + 2 * i + 1]);
        }
        float h = 0.f, c = 0.f;

        for (int s = 0; s < nsteps; s++) {
            if ((s & (GROUP - 1)) == 0) {
                const int g = s >> 4;
                while (*vf0 < g) { __nanosleep(32); }          // xg1 ready (stage1, 3 ahead)
                if (g >= RING / GROUP) {
                    while (*vf2 < g - RING / GROUP) { __nanosleep(32); }  // ring1 consumer
                }
                __threadfence_block();
            }
            const int sl = s & (RING - 1);

            const float4 pre = *(const float4*)&ring0[sl][k][0];

            u64 acc[4];
            acc[0] = pk2(pre.x, 0.f);
            acc[1] = pk2(pre.y, 0.f);
            acc[2] = pk2(pre.z, 0.f);
            acc[3] = pk2(pre.w, 0.f);
            #pragma unroll
            for (int i = 0; i < HID / 2; i++) {
                const float h0 = __shfl_sync(0xffffffffu, h, 2 * i);
                const float h1 = __shfl_sync(0xffffffffu, h, 2 * i + 1);
                const u64 hp = pk2(h0, h1);
                #pragma unroll
                for (int g = 0; g < 4; g++) acc[g] = fma2(hp, whhp[g][i], acc[g]);
            }
            float pa[4];
            #pragma unroll
            for (int g = 0; g < 4; g++) { float lo, hi; up2(acc[g], lo, hi); pa[g] = lo + hi; }

            const float ig = sigf(pa[0]);
            const float fg = sigf(pa[1]);
            const float gg = tanhf_(pa[2]);
            const float og = sigf(pa[3]);
            c = fg * c + ig * gg;
            h = og * tanhf_(c);

            if (active) ring1[sl][k] = h;

            if ((s & (GROUP - 1)) == GROUP - 1) {
                __threadfence_block();
                if (lane == 0) *vf1 = s >> 4;
            }
        }
    } else if (warp == 1) {
        // ==== stage 1: layer-1 x-projection (3 groups ahead) + layer-2 input proj ====
        u64   wi1p[4][4];   // layer-1 input weights, j-pairs (j=0..7)
        float wi1s[4];      // j=8 scalar
        float bb1[4];
        u64   wi2p[4][HID / 2];
        float bb2[4];
        #pragma unroll
        for (int g = 0; g < 4; g++) {
            const int row = g * HID + k;
            #pragma unroll
            for (int i = 0; i < 4; i++)
                wi1p[g][i] = pk2(w_ih1[row * INP + 2 * i], w_ih1[row * INP + 2 * i + 1]);
            wi1s[g] = w_ih1[row * INP + 8];
            bb1[g]  = b1[row];
            #pragma unroll
            for (int i = 0; i < HID / 2; i++)
                wi2p[g][i] = pk2(w_ih2[row * HID + 2 * i], w_ih2[row * HID + 2 * i + 1]);
            bb2[g] = b2[row];
        }

        // ---- xproj helper (computes layer-1 input preacts for step ss) ----
        auto xproj = [&](int ss) {
            const long base = (long)(start + ss) * INP;
            float xv[INP];
            #pragma unroll
            for (int j = 0; j < INP; j++) xv[j] = x[base + j];
            u64 xp[4];
            #pragma unroll
            for (int i = 0; i < 4; i++) xp[i] = pk2(xv[2 * i], xv[2 * i + 1]);
            float pr[4];
            #pragma unroll
            for (int g = 0; g < 4; g++) {
                u64 a = pk2(bb1[g], 0.f);
                #pragma unroll
                for (int i = 0; i < 4; i++) a = fma2(xp[i], wi1p[g][i], a);
                float lo, hi; up2(a, lo, hi);
                pr[g] = fmaf(xv[8], wi1s[g], lo + hi);
            }
            if (active)
                *(float4*)&ring0[ss & (RING - 1)][k][0] = make_float4(pr[0], pr[1], pr[2], pr[3]);
        };

        // prefill: first 3 groups of xg1
        for (int s = 0; s < AHEAD; s++) xproj(s);
        __threadfence_block();
        if (lane == 0) *vf0 = AHEAD / GROUP - 1;   // groups 0..2 ready

        for (int s = 0; s < nsteps; s++) {
            if ((s & (GROUP - 1)) == 0) {
                const int g = s >> 4;
                while (*vf1 < g) { __nanosleep(32); }          // h1 ready
                if (g >= RING / GROUP) {
                    while (*vf3 < g - RING / GROUP) { __nanosleep(32); }  // ring2 consumer
                }
                __threadfence_block();
            }
            const int sl = s & (RING - 1);

            if (s + AHEAD < nsteps) xproj(s + AHEAD);

            // layer-2 input projection from h1 (read as packed pairs, broadcast LDS)
            const u64* hp = (const u64*)&ring1[sl][0];
            u64 acc[4];
            #pragma unroll
            for (int g = 0; g < 4; g++) acc[g] = pk2(bb2[g], 0.f);
            #pragma unroll
            for (int i = 0; i < HID / 2; i++) {
                const u64 hpi = hp[i];
                #pragma unroll
                for (int g = 0; g < 4; g++) acc[g] = fma2(hpi, wi2p[g][i], acc[g]);
            }
            float pr[4];
            #pragma unroll
            for (int g = 0; g < 4; g++) { float lo, hi; up2(acc[g], lo, hi); pr[g] = lo + hi; }
            if (active)
                *(float4*)&ring2[sl][k][0] = make_float4(pr[0], pr[1], pr[2], pr[3]);

            if ((s & (GROUP - 1)) == GROUP - 1) {
                const int g = s >> 4;
                __threadfence_block();
                if (lane == 0) { *vf2 = g; *vf0 = g + AHEAD / GROUP; }
            }
        }
    } else {
        // ==== stage 2: layer-2 recurrence + output projection ====
        u64 whhp[4][HID / 2];
        #pragma unroll
        for (int g = 0; g < 4; g++) {
            const int row = g * HID + k;
            #pragma unroll
            for (int i = 0; i < HID / 2; i++)
                whhp[g][i] = pk2(w_hh2[row * HID + 2 * i], w_hh2[row * HID + 2 * i + 1]);
        }
        const float wp = active ? w_p[k] : 0.f;
        const float bp = b_p[0];
        float h = 0.f, c = 0.f;

        for (int s = 0; s < nsteps; s++) {
            if ((s & (GROUP - 1)) == 0) {
                const int g = s >> 4;
                while (*vf2 < g) { __nanosleep(32); }
                __threadfence_block();
            }
            const int t  = start + s;
            const int sl = s & (RING - 1);

            const float4 pre = *(const float4*)&ring2[sl][k][0];

            u64 acc[4];
            acc[0] = pk2(pre.x, 0.f);
            acc[1] = pk2(pre.y, 0.f);
            acc[2] = pk2(pre.z, 0.f);
            acc[3] = pk2(pre.w, 0.f);
            #pragma unroll
            for (int i = 0; i < HID / 2; i++) {
                const float h0 = __shfl_sync(0xffffffffu, h, 2 * i);
                const float h1 = __shfl_sync(0xffffffffu, h, 2 * i + 1);
                const u64 hp = pk2(h0, h1);
                #pragma unroll
                for (int g = 0; g < 4; g++) acc[g] = fma2(hp, whhp[g][i], acc[g]);
            }
            float pa[4];
            #pragma unroll
            for (int g = 0; g < 4; g++) { float lo, hi; up2(acc[g], lo, hi); pa[g] = lo + hi; }

            const float ig = sigf(pa[0]);
            const float fg = sigf(pa[1]);
            const float gg = tanhf_(pa[2]);
            const float og = sigf(pa[3]);
            c = fg * c + ig * gg;
            h = og * tanhf_(c);

            if (t >= out_begin) {
                float p = active ? (wp * h) : 0.f;
                #pragma unroll
                for (int off = 16; off; off >>= 1)
                    p += __shfl_down_sync(0xffffffffu, p, off);
                if (lane == 0) out[t] = p + bp;
            }

            if ((s & (GROUP - 1)) == GROUP - 1) {
                __threadfence_block();
                if (lane == 0) *vf3 = s >> 4;
            }
        }
    }
}

extern "C" void kernel_launch(void* const* d_in, const int* in_sizes, int n_in,
                              void* d_out, int out_size)
{
    const float* x     = (const float*)d_in[0];
    const float* w_ih1 = (const float*)d_in[1];
    const float* w_hh1 = (const float*)d_in[2];
    const float* b1    = (const float*)d_in[3];
    const float* w_ih2 = (const float*)d_in[4];
    const float* w_hh2 = (const float*)d_in[5];
    const float* b2    = (const float*)d_in[6];
    const float* w_p   = (const float*)d_in[7];
    const float* b_p   = (const float*)d_in[8];
    float* out = (float*)d_out;

    lstm_kernel<<<NBLK, 96>>>(x, w_ih1, w_hh1, b1, w_ih2, w_hh2, b2, w_p, b_p, out);
}

// round 7
// speedup vs baseline: 1.5070x; 1.0242x over previous
#include <cuda_runtime.h>

#define SEQ     262144
#define HID     20
#define INP     9
#define CH      448            // output chunk per block
#define WARM    64             // warmup steps
#define GROUP   16             // sync granularity (steps)
#define RING0   64             // xg1 ring depth (4 groups)
#define RING12  32             // h1 / l2-preact ring depth (2 groups)
#define RINGH   64             // h2 ring depth (4 groups)
#define AHEAD   48             // xproj runs 3 groups ahead
#define NBLK    ((SEQ + CH - 1) / CH)   // 586 blocks

typedef unsigned long long u64;

__device__ __forceinline__ u64 pk2(float lo, float hi) {
    u64 r; asm("mov.b64 %0,{%1,%2};" : "=l"(r) : "f"(lo), "f"(hi)); return r;
}
__device__ __forceinline__ void up2(u64 v, float& lo, float& hi) {
    asm("mov.b64 {%0,%1},%2;" : "=f"(lo), "=f"(hi) : "l"(v));
}
__device__ __forceinline__ u64 fma2(u64 a, u64 b, u64 c) {
    u64 d; asm("fma.rn.f32x2 %0,%1,%2,%3;" : "=l"(d) : "l"(a), "l"(b), "l"(c)); return d;
}
__device__ __forceinline__ float sigf(float v) {
    return __fdividef(1.f, 1.f + __expf(-v));
}
__device__ __forceinline__ float tanhf_(float v) {
    return 1.f - __fdividef(2.f, __expf(2.f * v) + 1.f);
}

__global__ void __launch_bounds__(128, 4) lstm_kernel(
    const float* __restrict__ x,
    const float* __restrict__ w_ih1, const float* __restrict__ w_hh1, const float* __restrict__ b1,
    const float* __restrict__ w_ih2, const float* __restrict__ w_hh2, const float* __restrict__ b2,
    const float* __restrict__ w_p,  const float* __restrict__ b_p,
    float* __restrict__ out)
{
    __shared__ __align__(16) float ring0[RING0][HID][4];   // l1 input preacts (incl b1)
    __shared__ __align__(16) float ring1[RING12][HID];     // h1
    __shared__ __align__(16) float ring2[RING12][HID][4];  // l2 input preacts (incl b2)
    __shared__ __align__(16) float ringh[RINGH][HID];      // h2
    __shared__ int f0x, f1, f2, f3, f4;

    const int tid  = threadIdx.x;
    const int warp = tid >> 5;
    const int lane = tid & 31;
    const int k    = (lane < HID) ? lane : (HID - 1);
    const bool active = (lane < HID);
    const int stage = (warp + (int)(blockIdx.x / 148)) & 3;

    if (tid == 0) { f0x = -1; f1 = -1; f2 = -1; f3 = -1; f4 = -1; }
    __syncthreads();

    const int blk       = blockIdx.x;
    const int out_begin = blk * CH;
    const int out_end   = (out_begin + CH < SEQ) ? (out_begin + CH) : SEQ;
    const int start     = (blk == 0) ? 0 : (out_begin - WARM);
    const int nsteps    = out_end - start;        // multiple of GROUP
    const int ngroups   = nsteps >> 4;

    volatile int* vf0 = &f0x;
    volatile int* vf1 = &f1;
    volatile int* vf2 = &f2;
    volatile int* vf3 = &f3;
    volatile int* vf4 = &f4;

    if (stage == 0) {
        // ===== S0: l1 x-projection (AHEAD ahead) + output projection =====
        u64   wi1p[4][4];
        float wi1s[4], bb1[4];
        #pragma unroll
        for (int g = 0; g < 4; g++) {
            const int row = g * HID + k;
            #pragma unroll
            for (int i = 0; i < 4; i++)
                wi1p[g][i] = pk2(w_ih1[row * INP + 2 * i], w_ih1[row * INP + 2 * i + 1]);
            wi1s[g] = w_ih1[row * INP + 8];
            bb1[g]  = b1[row];
        }
        const float wp = active ? w_p[k] : 0.f;
        const float bp = b_p[0];

        auto xproj = [&](int ss) {
            const int base = (start + ss) * INP;
            float xv[INP];
            #pragma unroll
            for (int j = 0; j < INP; j++) xv[j] = x[base + j];
            u64 xp[4];
            #pragma unroll
            for (int i = 0; i < 4; i++) xp[i] = pk2(xv[2 * i], xv[2 * i + 1]);
            float pr[4];
            #pragma unroll
            for (int g = 0; g < 4; g++) {
                u64 a = pk2(bb1[g], 0.f);
                #pragma unroll
                for (int i = 0; i < 4; i++) a = fma2(xp[i], wi1p[g][i], a);
                float lo, hi; up2(a, lo, hi);
                pr[g] = fmaf(xv[8], wi1s[g], lo + hi);
            }
            if (active)
                *(float4*)&ring0[ss & (RING0 - 1)][k][0] = make_float4(pr[0], pr[1], pr[2], pr[3]);
        };

        // prefill groups 0..2
        for (int s = 0; s < AHEAD && s < nsteps; s++) xproj(s);
        __threadfence_block();
        if (lane == 0) *vf0 = AHEAD / GROUP - 1;

        for (int gl = 0; gl < ngroups; gl++) {
            // xproj group gl+3 (ring0 depth 4: overwrites group gl-1)
            while (*vf1 < gl - 1) { __nanosleep(32); }
            const int xg = gl + AHEAD / GROUP;
            if (xg < ngroups) {
                const int sb = xg << 4;
                #pragma unroll 2
                for (int i = 0; i < GROUP; i++) xproj(sb + i);
            }
            __threadfence_block();
            if (lane == 0) *vf0 = xg;

            // output projection for group gl (skip pure-warmup groups)
            const int tg = start + (gl << 4);
            if (tg + GROUP - 1 >= out_begin) {
                while (*vf3 < gl) { __nanosleep(32); }
                __threadfence_block();
                #pragma unroll 2
                for (int i = 0; i < GROUP; i++) {
                    const int t = tg + i;
                    if (t >= out_begin) {
                        const int sl = ((gl << 4) + i) & (RINGH - 1);
                        float p = active ? (wp * ringh[sl][k]) : 0.f;
                        #pragma unroll
                        for (int off = 16; off; off >>= 1)
                            p += __shfl_down_sync(0xffffffffu, p, off);
                        if (lane == 0) out[t] = p + bp;
                    }
                }
            }
            __threadfence_block();
            if (lane == 0) *vf4 = gl;
        }
    } else if (stage == 1) {
        // ===== S1: layer-1 recurrence =====
        u64 whhp[4][HID / 2];
        #pragma unroll
        for (int g = 0; g < 4; g++) {
            const int row = g * HID + k;
            #pragma unroll
            for (int i = 0; i < HID / 2; i++)
                whhp[g][i] = pk2(w_hh1[row * HID + 2 * i], w_hh1[row * HID + 2 * i + 1]);
        }
        float h = 0.f, c = 0.f;

        for (int s = 0; s < nsteps; s++) {
            if ((s & (GROUP - 1)) == 0) {
                const int g = s >> 4;
                while (*vf0 < g) { __nanosleep(32); }            // xproj ready
                while (*vf2 < g - RING12 / GROUP) { __nanosleep(32); }  // ring1 free
                __threadfence_block();
            }
            const float4 pre = *(const float4*)&ring0[s & (RING0 - 1)][k][0];

            u64 acc[4];
            acc[0] = pk2(pre.x, 0.f); acc[1] = pk2(pre.y, 0.f);
            acc[2] = pk2(pre.z, 0.f); acc[3] = pk2(pre.w, 0.f);
            #pragma unroll
            for (int i = 0; i < HID / 2; i++) {
                const float h0 = __shfl_sync(0xffffffffu, h, 2 * i);
                const float h1 = __shfl_sync(0xffffffffu, h, 2 * i + 1);
                const u64 hp = pk2(h0, h1);
                #pragma unroll
                for (int g = 0; g < 4; g++) acc[g] = fma2(hp, whhp[g][i], acc[g]);
            }
            float pa[4];
            #pragma unroll
            for (int g = 0; g < 4; g++) { float lo, hi; up2(acc[g], lo, hi); pa[g] = lo + hi; }

            const float ig = sigf(pa[0]);
            const float fg = sigf(pa[1]);
            const float gg = tanhf_(pa[2]);
            const float og = sigf(pa[3]);
            c = fg * c + ig * gg;
            h = og * tanhf_(c);

            if (active) ring1[s & (RING12 - 1)][k] = h;

            if ((s & (GROUP - 1)) == GROUP - 1) {
                __threadfence_block();
                if (lane == 0) *vf1 = s >> 4;
            }
        }
    } else if (stage == 2) {
        // ===== S2: layer-2 input projection =====
        u64   wi2p[4][HID / 2];
        float bb2[4];
        #pragma unroll
        for (int g = 0; g < 4; g++) {
            const int row = g * HID + k;
            #pragma unroll
            for (int i = 0; i < HID / 2; i++)
                wi2p[g][i] = pk2(w_ih2[row * HID + 2 * i], w_ih2[row * HID + 2 * i + 1]);
            bb2[g] = b2[row];
        }

        for (int s = 0; s < nsteps; s++) {
            if ((s & (GROUP - 1)) == 0) {
                const int g = s >> 4;
                while (*vf1 < g) { __nanosleep(32); }            // h1 ready
                while (*vf3 < g - RING12 / GROUP) { __nanosleep(32); }  // ring2 free
                __threadfence_block();
            }
            const int sl = s & (RING12 - 1);
            const u64* hp = (const u64*)&ring1[sl][0];

            u64 acc[4];
            #pragma unroll
            for (int g = 0; g < 4; g++) acc[g] = pk2(bb2[g], 0.f);
            #pragma unroll
            for (int i = 0; i < HID / 2; i++) {
                const u64 hpi = hp[i];
                #pragma unroll
                for (int g = 0; g < 4; g++) acc[g] = fma2(hpi, wi2p[g][i], acc[g]);
            }
            float pr[4];
            #pragma unroll
            for (int g = 0; g < 4; g++) { float lo, hi; up2(acc[g], lo, hi); pr[g] = lo + hi; }
            if (active)
                *(float4*)&ring2[sl][k][0] = make_float4(pr[0], pr[1], pr[2], pr[3]);

            if ((s & (GROUP - 1)) == GROUP - 1) {
                __threadfence_block();
                if (lane == 0) *vf2 = s >> 4;
            }
        }
    } else {
        // ===== S3: layer-2 recurrence =====
        u64 whhp[4][HID / 2];
        #pragma unroll
        for (int g = 0; g < 4; g++) {
            const int row = g * HID + k;
            #pragma unroll
            for (int i = 0; i < HID / 2; i++)
                whhp[g][i] = pk2(w_hh2[row * HID + 2 * i], w_hh2[row * HID + 2 * i + 1]);
        }
        float h = 0.f, c = 0.f;

        for (int s = 0; s < nsteps; s++) {
            if ((s & (GROUP - 1)) == 0) {
                const int g = s >> 4;
                while (*vf2 < g) { __nanosleep(32); }            // l2 preacts ready
                while (*vf4 < g - RINGH / GROUP) { __nanosleep(32); }   // ringh free
                __threadfence_block();
            }
            const float4 pre = *(const float4*)&ring2[s & (RING12 - 1)][k][0];

            u64 acc[4];
            acc[0] = pk2(pre.x, 0.f); acc[1] = pk2(pre.y, 0.f);
            acc[2] = pk2(pre.z, 0.f); acc[3] = pk2(pre.w, 0.f);
            #pragma unroll
            for (int i = 0; i < HID / 2; i++) {
                const float h0 = __shfl_sync(0xffffffffu, h, 2 * i);
                const float h1 = __shfl_sync(0xffffffffu, h, 2 * i + 1);
                const u64 hp = pk2(h0, h1);
                #pragma unroll
                for (int g = 0; g < 4; g++) acc[g] = fma2(hp, whhp[g][i], acc[g]);
            }
            float pa[4];
            #pragma unroll
            for (int g = 0; g < 4; g++) { float lo, hi; up2(acc[g], lo, hi); pa[g] = lo + hi; }

            const float ig = sigf(pa[0]);
            const float fg = sigf(pa[1]);
            const float gg = tanhf_(pa[2]);
            const float og = sigf(pa[3]);
            c = fg * c + ig * gg;
            h = og * tanhf_(c);

            if (active) ringh[s & (RINGH - 1)][k] = h;

            if ((s & (GROUP - 1)) == GROUP - 1) {
                __threadfence_block();
                if (lane == 0) *vf3 = s >> 4;
            }
        }
    }
}

extern "C" void kernel_launch(void* const* d_in, const int* in_sizes, int n_in,
                              void* d_out, int out_size)
{
    const float* x     = (const float*)d_in[0];
    const float* w_ih1 = (const float*)d_in[1];
    const float* w_hh1 = (const float*)d_in[2];
    const float* b1    = (const float*)d_in[3];
    const float* w_ih2 = (const float*)d_in[4];
    const float* w_hh2 = (const float*)d_in[5];
    const float* b2    = (const float*)d_in[6];
    const float* w_p   = (const float*)d_in[7];
    const float* b_p   = (const float*)d_in[8];
    float* out = (float*)d_out;

    lstm_kernel<<<NBLK, 128>>>(x, w_ih1, w_hh1, b1, w_ih2, w_hh2, b2, w_p, b_p, out);
}